// round 17
// baseline (speedup 1.0000x reference)
#include <cuda_runtime.h>
#include <cuda_bf16.h>
#include <climits>
#include <cstdint>

#define N_NODES    50000
#define N_EDGES    800000
#define CH         128
#define OUT_CH     10
#define NUM_GRAPHS 128
#define SCAN_THREADS 1024
#define SCAN_CHUNK  ((N_NODES + SCAN_THREADS - 1) / SCAN_THREADS)   // 49

// GEMM tensor-core tile config
#define BM 64
#define SMEM_AH 0
#define SMEM_AL 17408
#define SMEM_BH 34816
#define SMEM_BL 69632
#define SMEM_TOT 104448   // bytes

// -------- persistent scratch (device globals; referenced ONLY inside kernels) --------
__device__ int g_e64_flag;
__device__ int g_b64_flag;
__device__ __align__(16) int   g_eidx[2 * N_EDGES];
__device__ __align__(16) int   g_batch[N_NODES];
__device__ __align__(16) int   g_deg_i[N_NODES];
__device__ __align__(16) int   g_rowptr[N_NODES + 1];
__device__ __align__(16) int   g_cursor[N_NODES];
__device__ __align__(16) float g_dinv[N_NODES];
__device__ __align__(16) int   g_csrc[N_EDGES];
__device__ __align__(16) float g_cnorm[N_EDGES];
__device__ __align__(16) float g_h[(size_t)N_NODES * CH];
__device__ __align__(16) float g_agg[(size_t)N_NODES * CH];
__device__ __align__(16) int   g_begin[NUM_GRAPHS];
__device__ __align__(16) int   g_end[NUM_GRAPHS];

// ---------------------------------------------------------------------------
__global__ __launch_bounds__(512) void detect_kernel(
    const unsigned int* __restrict__ ebuf, const unsigned int* __restrict__ bbuf)
{
    int t = threadIdx.x;
    int bad_e = (ebuf[2 * t + 1] != 0u);
    int widx = (N_NODES - 1024) + 2 * t + 1;
    int bad_b = (bbuf[widx] != 0u);
    int any_e = __syncthreads_or(bad_e);
    int any_b = __syncthreads_or(bad_b);
    if (t == 0) { g_e64_flag = any_e ? 0 : 1; g_b64_flag = any_b ? 0 : 1; }
}

__global__ void conv_edges_kernel(const unsigned int* __restrict__ ebuf) {
    int i = blockIdx.x * blockDim.x + threadIdx.x;
    if (i >= 2 * N_EDGES) return;
    g_eidx[i] = g_e64_flag ? (int)ebuf[2 * i] : (int)ebuf[i];
}

__global__ void conv_batch_kernel(const unsigned int* __restrict__ bbuf) {
    int i = blockIdx.x * blockDim.x + threadIdx.x;
    if (i >= N_NODES) return;
    int v = g_b64_flag ? (int)bbuf[2 * i] : (int)bbuf[i];
    if ((unsigned)v >= NUM_GRAPHS) v = 0;
    g_batch[i] = v;
}

// ---------------------------------------------------------------------------
// split fp32 -> (hi, lo) bf16, packed 2-wide into u32
__device__ __forceinline__ void split_pack(float a, float b, uint32_t& hi, uint32_t& lo) {
    __nv_bfloat16 ha = __float2bfloat16(a), hb = __float2bfloat16(b);
    float ra = a - __bfloat162float(ha);
    float rb = b - __bfloat162float(hb);
    __nv_bfloat16 la = __float2bfloat16(ra), lb = __float2bfloat16(rb);
    hi = ((uint32_t)__bfloat16_as_ushort(hb) << 16) | (uint32_t)__bfloat16_as_ushort(ha);
    lo = ((uint32_t)__bfloat16_as_ushort(lb) << 16) | (uint32_t)__bfloat16_as_ushort(la);
}

#define LDSM4(r, addr) \
    asm volatile("ldmatrix.sync.aligned.m8n8.x4.shared.b16 {%0,%1,%2,%3}, [%4];" \
        : "=r"((r)[0]), "=r"((r)[1]), "=r"((r)[2]), "=r"((r)[3]) : "r"(addr))

#define LDSM2T(r, addr) \
    asm volatile("ldmatrix.sync.aligned.m8n8.x2.trans.shared.b16 {%0,%1}, [%2];" \
        : "=r"((r)[0]), "=r"((r)[1]) : "r"(addr))

#define MMA_BF16(c, a, b) \
    asm volatile("mma.sync.aligned.m16n8k16.row.col.f32.bf16.bf16.f32 " \
        "{%0,%1,%2,%3}, {%4,%5,%6,%7}, {%8,%9}, {%0,%1,%2,%3};" \
        : "+f"((c)[0]), "+f"((c)[1]), "+f"((c)[2]), "+f"((c)[3]) \
        : "r"((a)[0]), "r"((a)[1]), "r"((a)[2]), "r"((a)[3]), "r"((b)[0]), "r"((b)[1]))

// ---------------------------------------------------------------------------
// tensor-core GEMM: g_h = act(src (+bias if use_agg)) @ W
// src = X (use_agg=0) or g_agg (use_agg=1). Split-bf16 3-pass for fp32 accuracy.
// 64 rows/block, 256 threads, 8 warps: warp = (m16 tile) x (n64 strip).
__global__ __launch_bounds__(256) void gemm_tc_kernel(
    const float* __restrict__ Xext, const float* __restrict__ W,
    const float* __restrict__ bias, int use_agg)
{
    extern __shared__ char sm[];
    uint32_t* Ah = (uint32_t*)(sm + SMEM_AH);   // [64][68] u32 = [64][136] bf16
    uint32_t* Al = (uint32_t*)(sm + SMEM_AL);
    uint32_t* Bh = (uint32_t*)(sm + SMEM_BH);   // [128][68] u32
    uint32_t* Bl = (uint32_t*)(sm + SMEM_BL);

    const float* __restrict__ X = use_agg ? (const float*)g_agg : Xext;
    const int tid = threadIdx.x;
    const int rowBase = blockIdx.x * BM;

    // ---- stage A (64 x 128 fp32 -> hi/lo bf16, optional bias+relu) ----
#pragma unroll
    for (int i = 0; i < 8; i++) {
        int idx = tid + i * 256;
        int row = idx >> 5, c4 = idx & 31;
        int grow = rowBase + row;
        float4 v = make_float4(0.f, 0.f, 0.f, 0.f);
        if (grow < N_NODES) {
            v = *(const float4*)(X + (size_t)grow * CH + c4 * 4);
            if (use_agg) {
                float4 b = *(const float4*)(bias + c4 * 4);
                v.x = fmaxf(v.x + b.x, 0.f); v.y = fmaxf(v.y + b.y, 0.f);
                v.z = fmaxf(v.z + b.z, 0.f); v.w = fmaxf(v.w + b.w, 0.f);
            }
        }
        uint32_t h0, l0, h1, l1;
        split_pack(v.x, v.y, h0, l0);
        split_pack(v.z, v.w, h1, l1);
        Ah[row * 68 + c4 * 2] = h0;  Ah[row * 68 + c4 * 2 + 1] = h1;
        Al[row * 68 + c4 * 2] = l0;  Al[row * 68 + c4 * 2 + 1] = l1;
    }
    // ---- stage B = W (128 x 128) ----
#pragma unroll
    for (int i = 0; i < 16; i++) {
        int idx = tid + i * 256;
        int row = idx >> 5, c4 = idx & 31;
        float4 v = *(const float4*)(W + (size_t)row * CH + c4 * 4);
        uint32_t h0, l0, h1, l1;
        split_pack(v.x, v.y, h0, l0);
        split_pack(v.z, v.w, h1, l1);
        Bh[row * 68 + c4 * 2] = h0;  Bh[row * 68 + c4 * 2 + 1] = h1;
        Bl[row * 68 + c4 * 2] = l0;  Bl[row * 68 + c4 * 2 + 1] = l1;
    }
    __syncthreads();

    const int warp = tid >> 5, lane = tid & 31;
    const int m0 = (warp & 3) * 16;      // 4 m-warps
    const int n0 = (warp >> 2) * 64;     // 2 n-warps

    float c[8][4];
#pragma unroll
    for (int nt = 0; nt < 8; nt++)
#pragma unroll
        for (int j = 0; j < 4; j++) c[nt][j] = 0.f;

    uint32_t ahB = (uint32_t)__cvta_generic_to_shared(Ah);
    uint32_t alB = (uint32_t)__cvta_generic_to_shared(Al);
    uint32_t bhB = (uint32_t)__cvta_generic_to_shared(Bh);
    uint32_t blB = (uint32_t)__cvta_generic_to_shared(Bl);

#pragma unroll
    for (int kk = 0; kk < 8; kk++) {
        int arow = m0 + (lane & 15);
        int acol = kk * 16 + (lane >> 4) * 8;          // bf16 idx
        uint32_t aoff = (uint32_t)(arow * 136 + acol) * 2;
        uint32_t ah[4], al[4];
        LDSM4(ah, ahB + aoff);
        LDSM4(al, alB + aoff);

        int krow = kk * 16 + (lane & 15);              // lanes >=16 replicate, safe
#pragma unroll
        for (int nt = 0; nt < 8; nt++) {
            uint32_t boff = (uint32_t)(krow * 136 + n0 + nt * 8) * 2;
            uint32_t bh[2], bl[2];
            LDSM2T(bh, bhB + boff);
            LDSM2T(bl, blB + boff);
            MMA_BF16(c[nt], ah, bh);
            MMA_BF16(c[nt], ah, bl);
            MMA_BF16(c[nt], al, bh);
        }
    }

    // ---- writeback ----
    int r0 = rowBase + m0 + (lane >> 2);
    int cc = (lane & 3) * 2;
#pragma unroll
    for (int nt = 0; nt < 8; nt++) {
        int col = n0 + nt * 8 + cc;
        if (r0 < N_NODES)
            *(float2*)(g_h + (size_t)r0 * CH + col) = make_float2(c[nt][0], c[nt][1]);
        int r1 = r0 + 8;
        if (r1 < N_NODES)
            *(float2*)(g_h + (size_t)r1 * CH + col) = make_float2(c[nt][2], c[nt][3]);
    }
}

// ---------------------------------------------------------------------------
__global__ void zero_kernel() {
    int i = blockIdx.x * blockDim.x + threadIdx.x;
    if (i < N_NODES)      g_deg_i[i] = 0;
    if (i < NUM_GRAPHS) { g_begin[i] = INT_MAX; g_end[i] = 0; }
}

__global__ void deg_kernel() {
    int e = blockIdx.x * blockDim.x + threadIdx.x;
    if (e >= N_EDGES) return;
    unsigned d = (unsigned)g_eidx[N_EDGES + e];
    if (d < N_NODES) atomicAdd(&g_deg_i[d], 1);
}

__global__ __launch_bounds__(SCAN_THREADS) void scan_kernel() {
    __shared__ int sums[SCAN_THREADS];
    int tid = threadIdx.x;
    int base = tid * SCAN_CHUNK;
    int s = 0;
    for (int i = 0; i < SCAN_CHUNK; i++) {
        int idx = base + i;
        if (idx < N_NODES) s += g_deg_i[idx];
    }
    sums[tid] = s;
    __syncthreads();
    for (int off = 1; off < SCAN_THREADS; off <<= 1) {
        int v = (tid >= off) ? sums[tid - off] : 0;
        __syncthreads();
        sums[tid] += v;
        __syncthreads();
    }
    int run = (tid == 0) ? 0 : sums[tid - 1];
    for (int i = 0; i < SCAN_CHUNK; i++) {
        int idx = base + i;
        if (idx < N_NODES) {
            g_rowptr[idx] = run;
            g_cursor[idx] = run;
            run += g_deg_i[idx];
        }
    }
    if (tid == SCAN_THREADS - 1) g_rowptr[N_NODES] = run;
}

__global__ void dinv_kernel() {
    int i = blockIdx.x * blockDim.x + threadIdx.x;
    if (i < N_NODES) g_dinv[i] = rsqrtf((float)g_deg_i[i] + 1.0f);
}

__global__ void fill_kernel() {
    int e = blockIdx.x * blockDim.x + threadIdx.x;
    if (e >= N_EDGES) return;
    unsigned s = (unsigned)g_eidx[e];
    unsigned d = (unsigned)g_eidx[N_EDGES + e];
    if (s >= N_NODES || d >= N_NODES) return;
    int pos = atomicAdd(&g_cursor[d], 1);
    g_csrc[pos]  = (int)s;
    g_cnorm[pos] = g_dinv[s] * g_dinv[d];
}

__global__ void bounds_kernel() {
    int i = blockIdx.x * blockDim.x + threadIdx.x;
    if (i >= N_NODES) return;
    int g = g_batch[i];
    atomicMin(&g_begin[g], i);
    atomicMax(&g_end[g], i + 1);
}

// ---------------------------------------------------------------------------
// one warp per node, pure gather, unroll-2 (exact R11 kernel)
__global__ __launch_bounds__(256) void aggregate_kernel() {
    int node = (blockIdx.x * blockDim.x + threadIdx.x) >> 5;
    if (node >= N_NODES) return;
    int lane = threadIdx.x & 31;

    float dv = g_dinv[node];
    float w0 = dv * dv;
    float4 acc = *(const float4*)(g_h + (size_t)node * CH + lane * 4);
    acc.x *= w0; acc.y *= w0; acc.z *= w0; acc.w *= w0;

    int e   = g_rowptr[node];
    int end = g_rowptr[node + 1];

    for (; e + 1 < end; e += 2) {
        int   s0 = g_csrc[e];
        int   s1 = g_csrc[e + 1];
        float we0 = g_cnorm[e];
        float we1 = g_cnorm[e + 1];
        float4 v0 = *(const float4*)(g_h + (size_t)s0 * CH + lane * 4);
        float4 v1 = *(const float4*)(g_h + (size_t)s1 * CH + lane * 4);
        acc.x = fmaf(we0, v0.x, acc.x); acc.y = fmaf(we0, v0.y, acc.y);
        acc.z = fmaf(we0, v0.z, acc.z); acc.w = fmaf(we0, v0.w, acc.w);
        acc.x = fmaf(we1, v1.x, acc.x); acc.y = fmaf(we1, v1.y, acc.y);
        acc.z = fmaf(we1, v1.z, acc.z); acc.w = fmaf(we1, v1.w, acc.w);
    }
    if (e < end) {
        int   s0 = g_csrc[e];
        float we = g_cnorm[e];
        float4 v = *(const float4*)(g_h + (size_t)s0 * CH + lane * 4);
        acc.x = fmaf(we, v.x, acc.x); acc.y = fmaf(we, v.y, acc.y);
        acc.z = fmaf(we, v.z, acc.z); acc.w = fmaf(we, v.w, acc.w);
    }
    *(float4*)(g_agg + (size_t)node * CH + lane * 4) = acc;
}

// ---------------------------------------------------------------------------
// fused pool+classify (exact R11 kernel)
__global__ __launch_bounds__(CH) void poolcls_kernel(
    const float* __restrict__ b2, const float* __restrict__ Wc,
    const float* __restrict__ bc, float* __restrict__ out)
{
    __shared__ float s[CH];
    int g = blockIdx.x;
    int t = threadIdx.x;
    int b = g_begin[g], e = g_end[g];
    float bias = b2[t];
    float acc = 0.f;
    for (int i = b; i < e; i++)
        acc += fmaxf(g_agg[(size_t)i * CH + t] + bias, 0.f);
    int cnt = (e > b) ? (e - b) : 0;
    s[t] = acc / (float)((cnt > 0) ? cnt : 1);
    __syncthreads();
    if (t < OUT_CH) {
        float o = bc[t];
#pragma unroll 8
        for (int k = 0; k < CH; k++)
            o = fmaf(s[k], Wc[k * OUT_CH + t], o);
        out[g * OUT_CH + t] = o;
    }
}

// ---------------------------------------------------------------------------
extern "C" void kernel_launch(void* const* d_in, const int* in_sizes, int n_in,
                              void* d_out, int out_size)
{
    const void *px = nullptr, *pe = nullptr, *pb = nullptr;
    const void *pW1 = nullptr, *pW2 = nullptr, *pb1 = nullptr, *pb2 = nullptr;
    const void *pWc = nullptr, *pbc = nullptr;
    for (int i = 0; i < n_in; i++) {
        int sz = in_sizes[i];
        if      (sz == N_NODES * CH && !px) px = d_in[i];
        else if (sz == 2 * N_EDGES && !pe)  pe = d_in[i];
        else if (sz == N_NODES && !pb)      pb = d_in[i];
        else if (sz == CH * CH)      { if (!pW1) pW1 = d_in[i]; else if (!pW2) pW2 = d_in[i]; }
        else if (sz == CH)           { if (!pb1) pb1 = d_in[i]; else if (!pb2) pb2 = d_in[i]; }
        else if (sz == CH * OUT_CH && !pWc) pWc = d_in[i];
        else if (sz == OUT_CH && !pbc)      pbc = d_in[i];
    }
    const float*        x    = (const float*)px;
    const unsigned int* ebuf = (const unsigned int*)pe;
    const unsigned int* bbuf = (const unsigned int*)pb;
    const float*        W1   = (const float*)pW1;
    const float*        b1   = (const float*)pb1;
    const float*        W2   = (const float*)pW2;
    const float*        b2   = (const float*)pb2;
    const float*        Wc   = (const float*)pWc;
    const float*        bc   = (const float*)pbc;
    float*              out  = (float*)d_out;

    static bool attr_set = false;
    if (!attr_set) {
        cudaFuncSetAttribute(gemm_tc_kernel,
                             cudaFuncAttributeMaxDynamicSharedMemorySize, SMEM_TOT);
        attr_set = true;
    }

    const int NB_N  = (N_NODES + 255) / 256;
    const int NB_E  = (N_EDGES + 255) / 256;
    const int NB_AG = (N_NODES * 32 + 255) / 256;
    const int NB_TC = (N_NODES + BM - 1) / BM;

    detect_kernel<<<1, 512>>>(ebuf, bbuf);                                // 1
    conv_edges_kernel<<<(2 * N_EDGES + 255) / 256, 256>>>(ebuf);          // 2
    conv_batch_kernel<<<NB_N, 256>>>(bbuf);                               // 3
    gemm_tc_kernel<<<NB_TC, 256, SMEM_TOT>>>(x, W1, b1, 0);               // 4 <- profiled
    zero_kernel<<<NB_N, 256>>>();                                         // 5
    deg_kernel<<<NB_E, 256>>>();                                          // 6
    scan_kernel<<<1, SCAN_THREADS>>>();                                   // 7
    dinv_kernel<<<NB_N, 256>>>();                                         // 8
    fill_kernel<<<NB_E, 256>>>();                                         // 9
    bounds_kernel<<<NB_N, 256>>>();                                       // 10

    aggregate_kernel<<<NB_AG, 256>>>();                                   // 11
    gemm_tc_kernel<<<NB_TC, 256, SMEM_TOT>>>(nullptr, W2, b1, 1);         // 12
    aggregate_kernel<<<NB_AG, 256>>>();                                   // 13
    poolcls_kernel<<<NUM_GRAPHS, CH>>>(b2, Wc, bc, out);                  // 14
}